// round 1
// baseline (speedup 1.0000x reference)
#include <cuda_runtime.h>
#include <cuda_bf16.h>

#define Sd 2048
#define Bd 256
#define Hd 256
#define Pd 3

#define BM 64
#define BK 32

// ---------------- scratch (device globals; no allocation) ----------------
__device__ float g_hid2[Bd * Hd];              // Wh@ldh + bh + be
__device__ float g_ctx_part[8 * Bd * Hd];      // partial contexts
__device__ float g_h1[Bd * Hd];                // relu(gru@W1^T+b1)
__device__ float g_scale[Hd];                  // BN scale
__device__ float g_shift[Hd];                  // BN shift

__device__ __forceinline__ float sigmoidf_(float x) {
    return 1.0f / (1.0f + __expf(-x));
}

// ---------------- hid2[b,k] = sum_h ldh[b,h]*Wh[k,h] + bh[k] + be[k] -----
__global__ void hid2_kernel(const float* __restrict__ ldh,
                            const float* __restrict__ Wh,
                            const float* __restrict__ bh,
                            const float* __restrict__ be) {
    int b = blockIdx.x, tid = threadIdx.x, lane = tid & 31, warp = tid >> 5;
    __shared__ float hsm[Hd];
    hsm[tid] = ldh[b * Hd + tid];
    __syncthreads();
    for (int k = warp; k < Hd; k += 8) {
        float a = 0.f;
        #pragma unroll
        for (int t = 0; t < 8; t++)
            a += hsm[lane + 32 * t] * Wh[k * Hd + lane + 32 * t];
        #pragma unroll
        for (int o = 16; o; o >>= 1) a += __shfl_xor_sync(0xffffffffu, a, o);
        if (lane == 0) g_hid2[b * Hd + k] = a + bh[k] + be[k];
    }
}

// ---------------- fused energy GEMM --------------------------------------
// energy[b*S+s] = sum_k Wv[k] * sigmoid( (X @ We^T)[m,k] + hid2[b,k] ),
// m = s*B + b.  (bv dropped: softmax-invariant.)
__global__ __launch_bounds__(256, 2)
void energy_kernel(const float* __restrict__ X,    // [S*B, H]
                   const float* __restrict__ We,   // [H, H]
                   const float* __restrict__ Wv,   // [H]
                   float* __restrict__ out_attn) { // [B, S] (pre-softmax)
    __shared__ __align__(16) float Xs[BK][BM + 9];   // stride 73: conflict-free stores
    __shared__ __align__(16) float Ws[BK][Hd + 2];   // stride 258: 8B-aligned pairs

    const int tid = threadIdx.x;
    const int m0 = blockIdx.x * BM;
    const int row_group = tid >> 5;   // 0..7  -> rows row_group*8 .. +7
    const int col_group = tid & 31;   // cols: col_group*2 + 64*j, pairs

    unsigned long long acc[8][4];
    #pragma unroll
    for (int r = 0; r < 8; r++)
        #pragma unroll
        for (int j = 0; j < 4; j++) acc[r][j] = 0ull;

    for (int h0 = 0; h0 < Hd; h0 += BK) {
        __syncthreads();
        #pragma unroll
        for (int p = 0; p < 8; p++) {            // X tile: 64 rows x 32 k
            int i = tid + p * 256;
            int row = i >> 5, kk = i & 31;
            Xs[kk][row] = X[(m0 + row) * Hd + h0 + kk];
        }
        #pragma unroll
        for (int p = 0; p < 32; p++) {           // W tile: 256 cols x 32 k
            int i = tid + p * 256;
            int col = i >> 5, kk = i & 31;
            Ws[kk][col] = We[col * Hd + h0 + kk];
        }
        __syncthreads();

        #pragma unroll 8
        for (int kk = 0; kk < BK; kk++) {
            unsigned long long xp[8];
            #pragma unroll
            for (int r = 0; r < 8; r++) {
                float xv = Xs[kk][row_group * 8 + r];
                asm("mov.b64 %0, {%1, %1};" : "=l"(xp[r]) : "f"(xv));
            }
            unsigned long long wv[4];
            #pragma unroll
            for (int j = 0; j < 4; j++)
                wv[j] = *reinterpret_cast<const unsigned long long*>(
                            &Ws[kk][col_group * 2 + 64 * j]);
            #pragma unroll
            for (int r = 0; r < 8; r++)
                #pragma unroll
                for (int j = 0; j < 4; j++)
                    asm("fma.rn.f32x2 %0, %1, %2, %0;"
                        : "+l"(acc[r][j]) : "l"(xp[r]), "l"(wv[j]));
        }
    }

    // epilogue: +hid2, sigmoid, dot Wv, warp-reduce over the 32 col_groups
    #pragma unroll
    for (int r = 0; r < 8; r++) {
        int m = m0 + row_group * 8 + r;
        int b = m & (Bd - 1);
        int s = m >> 8;
        float partial = 0.f;
        #pragma unroll
        for (int j = 0; j < 4; j++) {
            float2 a = *reinterpret_cast<float2*>(&acc[r][j]);
            int c0 = col_group * 2 + 64 * j;
            float v0 = sigmoidf_(a.x + g_hid2[b * Hd + c0]);
            float v1 = sigmoidf_(a.y + g_hid2[b * Hd + c0 + 1]);
            partial += __ldg(&Wv[c0]) * v0 + __ldg(&Wv[c0 + 1]) * v1;
        }
        #pragma unroll
        for (int o = 16; o; o >>= 1)
            partial += __shfl_xor_sync(0xffffffffu, partial, o);
        if (col_group == 0) out_attn[b * Sd + s] = partial;
    }
}

// ---------------- softmax over s, per b, in-place on [B,S] ---------------
__global__ void softmax_kernel(float* __restrict__ attn) {
    int b = blockIdx.x, tid = threadIdx.x;
    float* row = attn + b * Sd;
    float v[8];
    float mx = -1e30f;
    #pragma unroll
    for (int t = 0; t < 8; t++) { v[t] = row[tid + 256 * t]; mx = fmaxf(mx, v[t]); }
    __shared__ float redm[8];
    __shared__ float reds[8];
    #pragma unroll
    for (int o = 16; o; o >>= 1) mx = fmaxf(mx, __shfl_xor_sync(0xffffffffu, mx, o));
    if ((tid & 31) == 0) redm[tid >> 5] = mx;
    __syncthreads();
    mx = redm[0];
    #pragma unroll
    for (int i = 1; i < 8; i++) mx = fmaxf(mx, redm[i]);
    float sum = 0.f;
    #pragma unroll
    for (int t = 0; t < 8; t++) { v[t] = __expf(v[t] - mx); sum += v[t]; }
    #pragma unroll
    for (int o = 16; o; o >>= 1) sum += __shfl_xor_sync(0xffffffffu, sum, o);
    if ((tid & 31) == 0) reds[tid >> 5] = sum;
    __syncthreads();
    sum = 0.f;
    #pragma unroll
    for (int i = 0; i < 8; i++) sum += reds[i];
    float inv = 1.f / sum;
    #pragma unroll
    for (int t = 0; t < 8; t++) row[tid + 256 * t] = v[t] * inv;
}

// ---------------- context partials: stream encoder_outputs ---------------
__global__ void ctx_part_kernel(const float* __restrict__ enc,
                                const float* __restrict__ attn) {
    int b = blockIdx.x, sc = blockIdx.y, h = threadIdx.x;
    int s0 = sc * 256;
    const float* wrow = attn + b * Sd + s0;
    const float* e = enc + (s0 * Bd + b) * Hd + h;
    float a0 = 0.f, a1 = 0.f, a2 = 0.f, a3 = 0.f;
    #pragma unroll 2
    for (int s = 0; s < 256; s += 4) {
        a0 += wrow[s + 0] * e[(s + 0) * (Bd * Hd)];
        a1 += wrow[s + 1] * e[(s + 1) * (Bd * Hd)];
        a2 += wrow[s + 2] * e[(s + 2) * (Bd * Hd)];
        a3 += wrow[s + 3] * e[(s + 3) * (Bd * Hd)];
    }
    g_ctx_part[(sc * Bd + b) * Hd + h] = (a0 + a1) + (a2 + a3);
}

__global__ void ctx_reduce_kernel(float* __restrict__ out_ctx) {
    int b = blockIdx.x, h = threadIdx.x;
    float acc = 0.f;
    #pragma unroll
    for (int sc = 0; sc < 8; sc++) acc += g_ctx_part[(sc * Bd + b) * Hd + h];
    out_ctx[b * Hd + h] = acc;
}

// ---------------- GRU cell ------------------------------------------------
__global__ void gru_kernel(const float* __restrict__ last_palette,
                           const float* __restrict__ ldh,
                           const float* __restrict__ ctx,
                           const float* __restrict__ W_ih,
                           const float* __restrict__ b_ih,
                           const float* __restrict__ W_hh,
                           const float* __restrict__ b_hh,
                           float* __restrict__ out_gru) {
    int b = blockIdx.x, tid = threadIdx.x, lane = tid & 31, warp = tid >> 5;
    __shared__ float xs[262];     // [palette(3) | context(256)]
    __shared__ float hs[Hd];
    __shared__ float gi[3 * Hd];
    __shared__ float gh[3 * Hd];
    if (tid < Pd) xs[tid] = last_palette[b * Pd + tid];
    xs[Pd + tid] = ctx[b * Hd + tid];
    hs[tid] = ldh[b * Hd + tid];
    __syncthreads();
    const int KX = Hd + Pd; // 259
    for (int k = warp; k < 3 * Hd; k += 8) {
        float a = 0.f;
        #pragma unroll
        for (int t = 0; t < 8; t++)
            a += xs[lane + 32 * t] * W_ih[k * KX + lane + 32 * t];
        if (lane < 3) a += xs[256 + lane] * W_ih[k * KX + 256 + lane];
        #pragma unroll
        for (int o = 16; o; o >>= 1) a += __shfl_xor_sync(0xffffffffu, a, o);
        if (lane == 0) gi[k] = a + b_ih[k];
        float c = 0.f;
        #pragma unroll
        for (int t = 0; t < 8; t++)
            c += hs[lane + 32 * t] * W_hh[k * Hd + lane + 32 * t];
        #pragma unroll
        for (int o = 16; o; o >>= 1) c += __shfl_xor_sync(0xffffffffu, c, o);
        if (lane == 0) gh[k] = c + b_hh[k];
    }
    __syncthreads();
    int k = tid;
    float r = sigmoidf_(gi[k] + gh[k]);
    float z = sigmoidf_(gi[Hd + k] + gh[Hd + k]);
    float n = tanhf(gi[2 * Hd + k] + r * gh[2 * Hd + k]);
    out_gru[b * Hd + k] = (1.f - z) * n + z * hs[k];
}

// ---------------- h1 = relu(gru @ W1^T + b1) ------------------------------
__global__ void h1_kernel(const float* __restrict__ gru,
                          const float* __restrict__ W1,
                          const float* __restrict__ b1) {
    int b = blockIdx.x, tid = threadIdx.x, lane = tid & 31, warp = tid >> 5;
    __shared__ float gs[Hd];
    gs[tid] = gru[b * Hd + tid];
    __syncthreads();
    for (int k = warp; k < Hd; k += 8) {
        float a = 0.f;
        #pragma unroll
        for (int t = 0; t < 8; t++)
            a += gs[lane + 32 * t] * W1[k * Hd + lane + 32 * t];
        #pragma unroll
        for (int o = 16; o; o >>= 1) a += __shfl_xor_sync(0xffffffffu, a, o);
        if (lane == 0) g_h1[b * Hd + k] = fmaxf(a + b1[k], 0.f);
    }
}

// ---------------- BatchNorm stats (training, biased var) -----------------
__global__ void bn_kernel(const float* __restrict__ gamma,
                          const float* __restrict__ beta) {
    int k = threadIdx.x; // 256 threads, one block
    float s = 0.f, sq = 0.f;
    for (int b = 0; b < Bd; b++) {
        float v = g_h1[b * Hd + k];
        s += v; sq += v * v;
    }
    float mu = s * (1.f / Bd);
    float var = sq * (1.f / Bd) - mu * mu;
    float rstd = rsqrtf(var + 1e-5f);
    float sc = rstd * gamma[k];
    g_scale[k] = sc;
    g_shift[k] = beta[k] - mu * sc;
}

// ---------------- palette = h1n @ W2^T + b2 -------------------------------
__global__ void palette_kernel(const float* __restrict__ W2,
                               const float* __restrict__ b2,
                               float* __restrict__ out_pal) {
    int b = blockIdx.x, lane = threadIdx.x & 31, p = threadIdx.x >> 5;
    if (p >= Pd) return;
    float a = 0.f;
    #pragma unroll
    for (int t = 0; t < 8; t++) {
        int h = lane + 32 * t;
        a += (g_h1[b * Hd + h] * g_scale[h] + g_shift[h]) * W2[p * Hd + h];
    }
    #pragma unroll
    for (int o = 16; o; o >>= 1) a += __shfl_xor_sync(0xffffffffu, a, o);
    if (lane == 0) out_pal[b * Pd + p] = a + b2[p];
}

// ---------------- launch ---------------------------------------------------
extern "C" void kernel_launch(void* const* d_in, const int* in_sizes, int n_in,
                              void* d_out, int out_size) {
    const float* last_palette = (const float*)d_in[0];
    const float* ldh          = (const float*)d_in[1];
    const float* enc          = (const float*)d_in[2];
    const float* We           = (const float*)d_in[3];
    const float* be           = (const float*)d_in[4];
    const float* Wh           = (const float*)d_in[5];
    const float* bh           = (const float*)d_in[6];
    const float* Wv           = (const float*)d_in[7];
    // d_in[8] = bv : softmax-invariant scalar, unused
    const float* W_ih         = (const float*)d_in[9];
    const float* b_ih         = (const float*)d_in[10];
    const float* W_hh         = (const float*)d_in[11];
    const float* b_hh         = (const float*)d_in[12];
    const float* W1           = (const float*)d_in[13];
    const float* b1           = (const float*)d_in[14];
    const float* gamma        = (const float*)d_in[15];
    const float* beta         = (const float*)d_in[16];
    const float* W2           = (const float*)d_in[17];
    const float* b2           = (const float*)d_in[18];

    float* out      = (float*)d_out;
    float* out_pal  = out;                              // [B,3]
    float* out_ctx  = out + Bd * Pd;                    // [1,B,1,H]
    float* out_gru  = out + Bd * Pd + Bd * Hd;          // [B,H]
    float* out_attn = out + Bd * Pd + 2 * Bd * Hd;      // [B,1,S]

    hid2_kernel<<<Bd, 256>>>(ldh, Wh, bh, be);
    energy_kernel<<<(Sd * Bd) / BM, 256>>>(enc, We, Wv, out_attn);
    softmax_kernel<<<Bd, 256>>>(out_attn);
    ctx_part_kernel<<<dim3(Bd, 8), 256>>>(enc, out_attn);
    ctx_reduce_kernel<<<Bd, 256>>>(out_ctx);
    gru_kernel<<<Bd, 256>>>(last_palette, ldh, out_ctx, W_ih, b_ih, W_hh, b_hh, out_gru);
    h1_kernel<<<Bd, 256>>>(out_gru, W1, b1);
    bn_kernel<<<1, 256>>>(gamma, beta);
    palette_kernel<<<Bd, 128>>>(W2, b2, out_pal);
}

// round 2
// speedup vs baseline: 2.9341x; 2.9341x over previous
#include <cuda_runtime.h>
#include <cuda_bf16.h>
#include <cstdint>

#define Sd 2048
#define Bd 256
#define Hd 256
#define Pd 3

// ---------------- scratch (device globals; no allocation) ----------------
__device__ float g_hid2[Bd * Hd];              // Wh@ldh + bh + be
__device__ float g_ctx_part[8 * Bd * Hd];      // partial contexts
__device__ float g_h1[Bd * Hd];                // relu(gru@W1^T+b1)
__device__ float g_scale[Hd];                  // BN scale
__device__ float g_shift[Hd];                  // BN shift

__device__ __forceinline__ float sigmoidf_(float x) {
    return 1.0f / (1.0f + __expf(-x));
}

// ---------------- hid2[b,k] = sum_h ldh[b,h]*Wh[k,h] + bh[k] + be[k] -----
__global__ void hid2_kernel(const float* __restrict__ ldh,
                            const float* __restrict__ Wh,
                            const float* __restrict__ bh,
                            const float* __restrict__ be) {
    int b = blockIdx.x, tid = threadIdx.x, lane = tid & 31, warp = tid >> 5;
    __shared__ float hsm[Hd];
    hsm[tid] = ldh[b * Hd + tid];
    __syncthreads();
    for (int k = warp; k < Hd; k += 8) {
        float a = 0.f;
        #pragma unroll
        for (int t = 0; t < 8; t++)
            a += hsm[lane + 32 * t] * Wh[k * Hd + lane + 32 * t];
        #pragma unroll
        for (int o = 16; o; o >>= 1) a += __shfl_xor_sync(0xffffffffu, a, o);
        if (lane == 0) g_hid2[b * Hd + k] = a + bh[k] + be[k];
    }
}

// ---------------- tensor-core energy kernel -------------------------------
// For fixed b, 128 s-rows: energy[b,s] = sum_k Wv[k]*sigmoid((X@We^T)[m,k]+hid2[b,k])
// X row m = (s*B + b). bf16 HMMA, fp32 accumulate. bv dropped (softmax-invariant).

#define XS_STRIDE 264          // 256 + 8 bf16 pad (16B), conflict-free ldmatrix
#define SMEM_X_BYTES (128 * XS_STRIDE * 2)
#define SMEM_B_BYTES (64 * XS_STRIDE * 2)
#define SMEM_TOTAL (SMEM_X_BYTES + SMEM_B_BYTES + 2 * Hd * 4)

__device__ __forceinline__ void ldsm_x4(uint32_t& r0, uint32_t& r1,
                                        uint32_t& r2, uint32_t& r3, uint32_t addr) {
    asm volatile("ldmatrix.sync.aligned.m8n8.x4.shared.b16 {%0,%1,%2,%3}, [%4];"
                 : "=r"(r0), "=r"(r1), "=r"(r2), "=r"(r3) : "r"(addr));
}
__device__ __forceinline__ void ldsm_x2(uint32_t& r0, uint32_t& r1, uint32_t addr) {
    asm volatile("ldmatrix.sync.aligned.m8n8.x2.shared.b16 {%0,%1}, [%2];"
                 : "=r"(r0), "=r"(r1) : "r"(addr));
}
__device__ __forceinline__ void mma16816(float* d, uint32_t a0, uint32_t a1,
                                         uint32_t a2, uint32_t a3,
                                         uint32_t b0, uint32_t b1) {
    asm volatile(
        "mma.sync.aligned.m16n8k16.row.col.f32.bf16.bf16.f32 "
        "{%0,%1,%2,%3},{%4,%5,%6,%7},{%8,%9},{%0,%1,%2,%3};"
        : "+f"(d[0]), "+f"(d[1]), "+f"(d[2]), "+f"(d[3])
        : "r"(a0), "r"(a1), "r"(a2), "r"(a3), "r"(b0), "r"(b1));
}

__global__ __launch_bounds__(256, 2)
void energy_mma_kernel(const float* __restrict__ X,    // [S*B, H]
                       const float* __restrict__ We,   // [H, H]
                       const float* __restrict__ Wv,   // [H]
                       float* __restrict__ out_attn) { // [B, S] pre-softmax
    extern __shared__ char smem[];
    __nv_bfloat16* Xs = (__nv_bfloat16*)smem;                        // [128][264]
    __nv_bfloat16* Bs = (__nv_bfloat16*)(smem + SMEM_X_BYTES);       // [64][264]
    float* hid2s = (float*)(smem + SMEM_X_BYTES + SMEM_B_BYTES);     // [256]
    float* wvs = hid2s + Hd;                                         // [256]

    const int tid = threadIdx.x;
    const int lane = tid & 31;
    const int warp = tid >> 5;           // 0..7, rows warp*16..+15
    const int s0 = blockIdx.x * 128;
    const int b = blockIdx.y;

    // ---- stage X tile (128 s-rows of 1KB each), convert fp32->bf16 ----
    #pragma unroll
    for (int it = 0; it < 32; it++) {
        int idx = tid + it * 256;        // 8192 float4 total
        int row = idx >> 6;              // 0..127
        int c4 = idx & 63;               // float4 index in row
        const float4* src = (const float4*)(X + ((size_t)(s0 + row) * Bd + b) * Hd);
        float4 v = src[c4];
        __nv_bfloat162 p0 = __floats2bfloat162_rn(v.x, v.y);
        __nv_bfloat162 p1 = __floats2bfloat162_rn(v.z, v.w);
        uint2 pk;
        pk.x = *(uint32_t*)&p0;
        pk.y = *(uint32_t*)&p1;
        *(uint2*)&Xs[row * XS_STRIDE + c4 * 4] = pk;
    }
    // hid2 row and Wv
    hid2s[tid] = g_hid2[b * Hd + tid];
    wvs[tid] = Wv[tid];

    const uint32_t xs_u32 = (uint32_t)__cvta_generic_to_shared(Xs);
    const uint32_t bs_u32 = (uint32_t)__cvta_generic_to_shared(Bs);
    const uint32_t aoff = xs_u32 + (uint32_t)(warp * 16 * XS_STRIDE) * 2
                        + (uint32_t)((lane & 15) * XS_STRIDE + (lane >> 4) * 8) * 2;
    const uint32_t boff = bs_u32
                        + (uint32_t)((lane & 7) * XS_STRIDE + ((lane >> 3) & 1) * 8) * 2;

    float p0 = 0.f, p1 = 0.f;   // per-row energy partials (rows warp*16+l/4, +8)

    for (int c = 0; c < 4; c++) {
        __syncthreads();   // previous chunk's MMAs done before overwrite (and X ready)
        // ---- stage B chunk: We rows c*64..c*64+63 ----
        #pragma unroll
        for (int it = 0; it < 16; it++) {
            int idx = tid + it * 256;    // 4096 float4
            int row = idx >> 6;          // 0..63
            int c4 = idx & 63;
            const float4* src = (const float4*)(We + ((size_t)(c * 64 + row)) * Hd);
            float4 v = src[c4];
            __nv_bfloat162 q0 = __floats2bfloat162_rn(v.x, v.y);
            __nv_bfloat162 q1 = __floats2bfloat162_rn(v.z, v.w);
            uint2 pk;
            pk.x = *(uint32_t*)&q0;
            pk.y = *(uint32_t*)&q1;
            *(uint2*)&Bs[row * XS_STRIDE + c4 * 4] = pk;
        }
        __syncthreads();

        float d[8][4];
        #pragma unroll
        for (int nt = 0; nt < 8; nt++)
            #pragma unroll
            for (int j = 0; j < 4; j++) d[nt][j] = 0.f;

        #pragma unroll
        for (int ks = 0; ks < 16; ks++) {
            uint32_t a0, a1, a2, a3;
            ldsm_x4(a0, a1, a2, a3, aoff + ks * 32);   // 16 bf16 = 32B per kstep
            #pragma unroll
            for (int nt = 0; nt < 8; nt++) {
                uint32_t b0, b1;
                ldsm_x2(b0, b1, boff + (uint32_t)(nt * 8 * XS_STRIDE) * 2 + ks * 32);
                mma16816(d[nt], a0, a1, a2, a3, b0, b1);
            }
        }

        // ---- epilogue for this 64-col chunk ----
        #pragma unroll
        for (int nt = 0; nt < 8; nt++) {
            int col = c * 64 + nt * 8 + 2 * (lane & 3);
            float h0 = hid2s[col], h1 = hid2s[col + 1];
            float w0 = wvs[col], w1 = wvs[col + 1];
            p0 += w0 * sigmoidf_(d[nt][0] + h0) + w1 * sigmoidf_(d[nt][1] + h1);
            p1 += w0 * sigmoidf_(d[nt][2] + h0) + w1 * sigmoidf_(d[nt][3] + h1);
        }
    }

    // reduce across the 4 lanes of each row group
    p0 += __shfl_xor_sync(0xffffffffu, p0, 1);
    p0 += __shfl_xor_sync(0xffffffffu, p0, 2);
    p1 += __shfl_xor_sync(0xffffffffu, p1, 1);
    p1 += __shfl_xor_sync(0xffffffffu, p1, 2);
    if ((lane & 3) == 0) {
        int q = lane >> 2;               // 0..7
        int row = warp * 16 + q;
        out_attn[b * Sd + s0 + row] = p0;
        out_attn[b * Sd + s0 + row + 8] = p1;
    }
}

// ---------------- softmax over s, per b, in-place on [B,S] ---------------
__global__ void softmax_kernel(float* __restrict__ attn) {
    int b = blockIdx.x, tid = threadIdx.x;
    float* row = attn + b * Sd;
    float v[8];
    float mx = -1e30f;
    #pragma unroll
    for (int t = 0; t < 8; t++) { v[t] = row[tid + 256 * t]; mx = fmaxf(mx, v[t]); }
    __shared__ float redm[8];
    __shared__ float reds[8];
    #pragma unroll
    for (int o = 16; o; o >>= 1) mx = fmaxf(mx, __shfl_xor_sync(0xffffffffu, mx, o));
    if ((tid & 31) == 0) redm[tid >> 5] = mx;
    __syncthreads();
    mx = redm[0];
    #pragma unroll
    for (int i = 1; i < 8; i++) mx = fmaxf(mx, redm[i]);
    float sum = 0.f;
    #pragma unroll
    for (int t = 0; t < 8; t++) { v[t] = __expf(v[t] - mx); sum += v[t]; }
    #pragma unroll
    for (int o = 16; o; o >>= 1) sum += __shfl_xor_sync(0xffffffffu, sum, o);
    if ((tid & 31) == 0) reds[tid >> 5] = sum;
    __syncthreads();
    sum = 0.f;
    #pragma unroll
    for (int i = 0; i < 8; i++) sum += reds[i];
    float inv = 1.f / sum;
    #pragma unroll
    for (int t = 0; t < 8; t++) row[tid + 256 * t] = v[t] * inv;
}

// ---------------- context partials: stream encoder_outputs ---------------
__global__ void ctx_part_kernel(const float* __restrict__ enc,
                                const float* __restrict__ attn) {
    int b = blockIdx.x, sc = blockIdx.y, h = threadIdx.x;
    int s0 = sc * 256;
    const float* wrow = attn + b * Sd + s0;
    const float* e = enc + ((size_t)s0 * Bd + b) * Hd + h;
    float a0 = 0.f, a1 = 0.f, a2 = 0.f, a3 = 0.f;
    #pragma unroll 2
    for (int s = 0; s < 256; s += 4) {
        a0 += wrow[s + 0] * e[(size_t)(s + 0) * (Bd * Hd)];
        a1 += wrow[s + 1] * e[(size_t)(s + 1) * (Bd * Hd)];
        a2 += wrow[s + 2] * e[(size_t)(s + 2) * (Bd * Hd)];
        a3 += wrow[s + 3] * e[(size_t)(s + 3) * (Bd * Hd)];
    }
    g_ctx_part[(sc * Bd + b) * Hd + h] = (a0 + a1) + (a2 + a3);
}

__global__ void ctx_reduce_kernel(float* __restrict__ out_ctx) {
    int b = blockIdx.x, h = threadIdx.x;
    float acc = 0.f;
    #pragma unroll
    for (int sc = 0; sc < 8; sc++) acc += g_ctx_part[(sc * Bd + b) * Hd + h];
    out_ctx[b * Hd + h] = acc;
}

// ---------------- GRU cell ------------------------------------------------
__global__ void gru_kernel(const float* __restrict__ last_palette,
                           const float* __restrict__ ldh,
                           const float* __restrict__ ctx,
                           const float* __restrict__ W_ih,
                           const float* __restrict__ b_ih,
                           const float* __restrict__ W_hh,
                           const float* __restrict__ b_hh,
                           float* __restrict__ out_gru) {
    int b = blockIdx.x, tid = threadIdx.x, lane = tid & 31, warp = tid >> 5;
    __shared__ float xs[262];     // [palette(3) | context(256)]
    __shared__ float hs[Hd];
    __shared__ float gi[3 * Hd];
    __shared__ float gh[3 * Hd];
    if (tid < Pd) xs[tid] = last_palette[b * Pd + tid];
    xs[Pd + tid] = ctx[b * Hd + tid];
    hs[tid] = ldh[b * Hd + tid];
    __syncthreads();
    const int KX = Hd + Pd; // 259
    for (int k = warp; k < 3 * Hd; k += 8) {
        float a = 0.f;
        #pragma unroll
        for (int t = 0; t < 8; t++)
            a += xs[lane + 32 * t] * W_ih[k * KX + lane + 32 * t];
        if (lane < 3) a += xs[256 + lane] * W_ih[k * KX + 256 + lane];
        #pragma unroll
        for (int o = 16; o; o >>= 1) a += __shfl_xor_sync(0xffffffffu, a, o);
        if (lane == 0) gi[k] = a + b_ih[k];
        float c = 0.f;
        #pragma unroll
        for (int t = 0; t < 8; t++)
            c += hs[lane + 32 * t] * W_hh[k * Hd + lane + 32 * t];
        #pragma unroll
        for (int o = 16; o; o >>= 1) c += __shfl_xor_sync(0xffffffffu, c, o);
        if (lane == 0) gh[k] = c + b_hh[k];
    }
    __syncthreads();
    int k = tid;
    float r = sigmoidf_(gi[k] + gh[k]);
    float z = sigmoidf_(gi[Hd + k] + gh[Hd + k]);
    float n = tanhf(gi[2 * Hd + k] + r * gh[2 * Hd + k]);
    out_gru[b * Hd + k] = (1.f - z) * n + z * hs[k];
}

// ---------------- h1 = relu(gru @ W1^T + b1) ------------------------------
__global__ void h1_kernel(const float* __restrict__ gru,
                          const float* __restrict__ W1,
                          const float* __restrict__ b1) {
    int b = blockIdx.x, tid = threadIdx.x, lane = tid & 31, warp = tid >> 5;
    __shared__ float gs[Hd];
    gs[tid] = gru[b * Hd + tid];
    __syncthreads();
    for (int k = warp; k < Hd; k += 8) {
        float a = 0.f;
        #pragma unroll
        for (int t = 0; t < 8; t++)
            a += gs[lane + 32 * t] * W1[k * Hd + lane + 32 * t];
        #pragma unroll
        for (int o = 16; o; o >>= 1) a += __shfl_xor_sync(0xffffffffu, a, o);
        if (lane == 0) g_h1[b * Hd + k] = fmaxf(a + b1[k], 0.f);
    }
}

// ---------------- BatchNorm stats (training, biased var) -----------------
__global__ void bn_kernel(const float* __restrict__ gamma,
                          const float* __restrict__ beta) {
    int k = threadIdx.x; // 256 threads, one block
    float s = 0.f, sq = 0.f;
    for (int b = 0; b < Bd; b++) {
        float v = g_h1[b * Hd + k];
        s += v; sq += v * v;
    }
    float mu = s * (1.f / Bd);
    float var = sq * (1.f / Bd) - mu * mu;
    float rstd = rsqrtf(var + 1e-5f);
    float sc = rstd * gamma[k];
    g_scale[k] = sc;
    g_shift[k] = beta[k] - mu * sc;
}

// ---------------- palette = h1n @ W2^T + b2 -------------------------------
__global__ void palette_kernel(const float* __restrict__ W2,
                               const float* __restrict__ b2,
                               float* __restrict__ out_pal) {
    int b = blockIdx.x, lane = threadIdx.x & 31, p = threadIdx.x >> 5;
    if (p >= Pd) return;
    float a = 0.f;
    #pragma unroll
    for (int t = 0; t < 8; t++) {
        int h = lane + 32 * t;
        a += (g_h1[b * Hd + h] * g_scale[h] + g_shift[h]) * W2[p * Hd + h];
    }
    #pragma unroll
    for (int o = 16; o; o >>= 1) a += __shfl_xor_sync(0xffffffffu, a, o);
    if (lane == 0) out_pal[b * Pd + p] = a + b2[p];
}

// ---------------- launch ---------------------------------------------------
extern "C" void kernel_launch(void* const* d_in, const int* in_sizes, int n_in,
                              void* d_out, int out_size) {
    const float* last_palette = (const float*)d_in[0];
    const float* ldh          = (const float*)d_in[1];
    const float* enc          = (const float*)d_in[2];
    const float* We           = (const float*)d_in[3];
    const float* be           = (const float*)d_in[4];
    const float* Wh           = (const float*)d_in[5];
    const float* bh           = (const float*)d_in[6];
    const float* Wv           = (const float*)d_in[7];
    // d_in[8] = bv : softmax-invariant scalar, unused
    const float* W_ih         = (const float*)d_in[9];
    const float* b_ih         = (const float*)d_in[10];
    const float* W_hh         = (const float*)d_in[11];
    const float* b_hh         = (const float*)d_in[12];
    const float* W1           = (const float*)d_in[13];
    const float* b1           = (const float*)d_in[14];
    const float* gamma        = (const float*)d_in[15];
    const float* beta         = (const float*)d_in[16];
    const float* W2           = (const float*)d_in[17];
    const float* b2           = (const float*)d_in[18];

    float* out      = (float*)d_out;
    float* out_pal  = out;                              // [B,3]
    float* out_ctx  = out + Bd * Pd;                    // [1,B,1,H]
    float* out_gru  = out + Bd * Pd + Bd * Hd;          // [B,H]
    float* out_attn = out + Bd * Pd + 2 * Bd * Hd;      // [B,1,S]

    static bool attr_done = false;
    if (!attr_done) {
        cudaFuncSetAttribute(energy_mma_kernel,
                             cudaFuncAttributeMaxDynamicSharedMemorySize, SMEM_TOTAL);
        attr_done = true;
    }

    hid2_kernel<<<Bd, 256>>>(ldh, Wh, bh, be);
    energy_mma_kernel<<<dim3(Sd / 128, Bd), 256, SMEM_TOTAL>>>(enc, We, Wv, out_attn);
    softmax_kernel<<<Bd, 256>>>(out_attn);
    ctx_part_kernel<<<dim3(Bd, 8), 256>>>(enc, out_attn);
    ctx_reduce_kernel<<<Bd, 256>>>(out_ctx);
    gru_kernel<<<Bd, 256>>>(last_palette, ldh, out_ctx, W_ih, b_ih, W_hh, b_hh, out_gru);
    h1_kernel<<<Bd, 256>>>(out_gru, W1, b1);
    bn_kernel<<<1, 256>>>(gamma, beta);
    palette_kernel<<<Bd, 128>>>(W2, b2, out_pal);
}

// round 3
// speedup vs baseline: 2.9368x; 1.0009x over previous
#include <cuda_runtime.h>
#include <cuda_bf16.h>
#include <cstdint>

#define Sd 2048
#define Bd 256
#define Hd 256
#define Pd 3

// ---------------- scratch (device globals; no allocation) ----------------
__device__ float g_hid2[Bd * Hd];              // Wh@ldh + bh + be
__device__ float g_ctx_part[8 * Bd * Hd];      // partial contexts
__device__ float g_h1[Bd * Hd];                // relu(gru@W1^T+b1)
__device__ float g_scale[Hd];                  // BN scale
__device__ float g_shift[Hd];                  // BN shift

__device__ __forceinline__ float sigmoidf_(float x) {
    return 1.0f / (1.0f + __expf(-x));
}

// ---------------- hid2[b,k] = sum_h ldh[b,h]*Wh[k,h] + bh[k] + be[k] -----
__global__ void hid2_kernel(const float* __restrict__ ldh,
                            const float* __restrict__ Wh,
                            const float* __restrict__ bh,
                            const float* __restrict__ be) {
    int b = blockIdx.x, tid = threadIdx.x, lane = tid & 31, warp = tid >> 5;
    __shared__ float hsm[Hd];
    hsm[tid] = ldh[b * Hd + tid];
    __syncthreads();
    for (int k = warp; k < Hd; k += 8) {
        float a = 0.f;
        #pragma unroll
        for (int t = 0; t < 8; t++)
            a += hsm[lane + 32 * t] * Wh[k * Hd + lane + 32 * t];
        #pragma unroll
        for (int o = 16; o; o >>= 1) a += __shfl_xor_sync(0xffffffffu, a, o);
        if (lane == 0) g_hid2[b * Hd + k] = a + bh[k] + be[k];
    }
}

// ---------------- tensor-core energy kernel -------------------------------
// For fixed b, 128 s-rows: energy[b,s] = sum_k Wv[k]*sigmoid((X@We^T)[m,k]+hid2[b,k])
// X row m = (s*B + b). bf16 HMMA, fp32 accumulate. bv dropped (softmax-invariant).

#define XS_STRIDE 264          // 256 + 8 bf16 pad (16B), conflict-free ldmatrix
#define SMEM_X_BYTES (128 * XS_STRIDE * 2)
#define SMEM_B_BYTES (64 * XS_STRIDE * 2)
#define SMEM_TOTAL (SMEM_X_BYTES + SMEM_B_BYTES + 2 * Hd * 4)

__device__ __forceinline__ void ldsm_x4(uint32_t& r0, uint32_t& r1,
                                        uint32_t& r2, uint32_t& r3, uint32_t addr) {
    asm volatile("ldmatrix.sync.aligned.m8n8.x4.shared.b16 {%0,%1,%2,%3}, [%4];"
                 : "=r"(r0), "=r"(r1), "=r"(r2), "=r"(r3) : "r"(addr));
}
__device__ __forceinline__ void ldsm_x2(uint32_t& r0, uint32_t& r1, uint32_t addr) {
    asm volatile("ldmatrix.sync.aligned.m8n8.x2.shared.b16 {%0,%1}, [%2];"
                 : "=r"(r0), "=r"(r1) : "r"(addr));
}
__device__ __forceinline__ void mma16816(float* d, uint32_t a0, uint32_t a1,
                                         uint32_t a2, uint32_t a3,
                                         uint32_t b0, uint32_t b1) {
    asm volatile(
        "mma.sync.aligned.m16n8k16.row.col.f32.bf16.bf16.f32 "
        "{%0,%1,%2,%3},{%4,%5,%6,%7},{%8,%9},{%0,%1,%2,%3};"
        : "+f"(d[0]), "+f"(d[1]), "+f"(d[2]), "+f"(d[3])
        : "r"(a0), "r"(a1), "r"(a2), "r"(a3), "r"(b0), "r"(b1));
}

__global__ __launch_bounds__(256, 2)
void energy_mma_kernel(const float* __restrict__ X,    // [S*B, H]
                       const float* __restrict__ We,   // [H, H]
                       const float* __restrict__ Wv,   // [H]
                       float* __restrict__ out_attn) { // [B, S] pre-softmax
    extern __shared__ char smem[];
    __nv_bfloat16* Xs = (__nv_bfloat16*)smem;                        // [128][264]
    __nv_bfloat16* Bs = (__nv_bfloat16*)(smem + SMEM_X_BYTES);       // [64][264]
    float* hid2s = (float*)(smem + SMEM_X_BYTES + SMEM_B_BYTES);     // [256]
    float* wvs = hid2s + Hd;                                         // [256]

    const int tid = threadIdx.x;
    const int lane = tid & 31;
    const int warp = tid >> 5;           // 0..7, rows warp*16..+15
    const int s0 = blockIdx.x * 128;
    const int b = blockIdx.y;

    // ---- stage X tile (128 s-rows of 1KB each), convert fp32->bf16 ----
    #pragma unroll
    for (int it = 0; it < 32; it++) {
        int idx = tid + it * 256;        // 8192 float4 total
        int row = idx >> 6;              // 0..127
        int c4 = idx & 63;               // float4 index in row
        const float4* src = (const float4*)(X + ((size_t)(s0 + row) * Bd + b) * Hd);
        float4 v = src[c4];
        __nv_bfloat162 p0 = __floats2bfloat162_rn(v.x, v.y);
        __nv_bfloat162 p1 = __floats2bfloat162_rn(v.z, v.w);
        uint2 pk;
        pk.x = *(uint32_t*)&p0;
        pk.y = *(uint32_t*)&p1;
        *(uint2*)&Xs[row * XS_STRIDE + c4 * 4] = pk;
    }
    // hid2 row and Wv
    hid2s[tid] = g_hid2[b * Hd + tid];
    wvs[tid] = Wv[tid];

    const uint32_t xs_u32 = (uint32_t)__cvta_generic_to_shared(Xs);
    const uint32_t bs_u32 = (uint32_t)__cvta_generic_to_shared(Bs);
    const uint32_t aoff = xs_u32 + (uint32_t)(warp * 16 * XS_STRIDE) * 2
                        + (uint32_t)((lane & 15) * XS_STRIDE + (lane >> 4) * 8) * 2;
    const uint32_t boff = bs_u32
                        + (uint32_t)((lane & 7) * XS_STRIDE + ((lane >> 3) & 1) * 8) * 2;

    float p0 = 0.f, p1 = 0.f;   // per-row energy partials (rows warp*16+l/4, +8)

    for (int c = 0; c < 4; c++) {
        __syncthreads();   // previous chunk's MMAs done before overwrite (and X ready)
        // ---- stage B chunk: We rows c*64..c*64+63 ----
        #pragma unroll
        for (int it = 0; it < 16; it++) {
            int idx = tid + it * 256;    // 4096 float4
            int row = idx >> 6;          // 0..63
            int c4 = idx & 63;
            const float4* src = (const float4*)(We + ((size_t)(c * 64 + row)) * Hd);
            float4 v = src[c4];
            __nv_bfloat162 q0 = __floats2bfloat162_rn(v.x, v.y);
            __nv_bfloat162 q1 = __floats2bfloat162_rn(v.z, v.w);
            uint2 pk;
            pk.x = *(uint32_t*)&q0;
            pk.y = *(uint32_t*)&q1;
            *(uint2*)&Bs[row * XS_STRIDE + c4 * 4] = pk;
        }
        __syncthreads();

        float d[8][4];
        #pragma unroll
        for (int nt = 0; nt < 8; nt++)
            #pragma unroll
            for (int j = 0; j < 4; j++) d[nt][j] = 0.f;

        #pragma unroll
        for (int ks = 0; ks < 16; ks++) {
            uint32_t a0, a1, a2, a3;
            ldsm_x4(a0, a1, a2, a3, aoff + ks * 32);   // 16 bf16 = 32B per kstep
            #pragma unroll
            for (int nt = 0; nt < 8; nt++) {
                uint32_t b0, b1;
                ldsm_x2(b0, b1, boff + (uint32_t)(nt * 8 * XS_STRIDE) * 2 + ks * 32);
                mma16816(d[nt], a0, a1, a2, a3, b0, b1);
            }
        }

        // ---- epilogue for this 64-col chunk ----
        #pragma unroll
        for (int nt = 0; nt < 8; nt++) {
            int col = c * 64 + nt * 8 + 2 * (lane & 3);
            float h0 = hid2s[col], h1 = hid2s[col + 1];
            float w0 = wvs[col], w1 = wvs[col + 1];
            p0 += w0 * sigmoidf_(d[nt][0] + h0) + w1 * sigmoidf_(d[nt][1] + h1);
            p1 += w0 * sigmoidf_(d[nt][2] + h0) + w1 * sigmoidf_(d[nt][3] + h1);
        }
    }

    // reduce across the 4 lanes of each row group
    p0 += __shfl_xor_sync(0xffffffffu, p0, 1);
    p0 += __shfl_xor_sync(0xffffffffu, p0, 2);
    p1 += __shfl_xor_sync(0xffffffffu, p1, 1);
    p1 += __shfl_xor_sync(0xffffffffu, p1, 2);
    if ((lane & 3) == 0) {
        int q = lane >> 2;               // 0..7
        int row = warp * 16 + q;
        out_attn[b * Sd + s0 + row] = p0;
        out_attn[b * Sd + s0 + row + 8] = p1;
    }
}

// ---------------- softmax over s, per b, in-place on [B,S] ---------------
__global__ void softmax_kernel(float* __restrict__ attn) {
    int b = blockIdx.x, tid = threadIdx.x;
    float* row = attn + b * Sd;
    float v[8];
    float mx = -1e30f;
    #pragma unroll
    for (int t = 0; t < 8; t++) { v[t] = row[tid + 256 * t]; mx = fmaxf(mx, v[t]); }
    __shared__ float redm[8];
    __shared__ float reds[8];
    #pragma unroll
    for (int o = 16; o; o >>= 1) mx = fmaxf(mx, __shfl_xor_sync(0xffffffffu, mx, o));
    if ((tid & 31) == 0) redm[tid >> 5] = mx;
    __syncthreads();
    mx = redm[0];
    #pragma unroll
    for (int i = 1; i < 8; i++) mx = fmaxf(mx, redm[i]);
    float sum = 0.f;
    #pragma unroll
    for (int t = 0; t < 8; t++) { v[t] = __expf(v[t] - mx); sum += v[t]; }
    #pragma unroll
    for (int o = 16; o; o >>= 1) sum += __shfl_xor_sync(0xffffffffu, sum, o);
    if ((tid & 31) == 0) reds[tid >> 5] = sum;
    __syncthreads();
    sum = 0.f;
    #pragma unroll
    for (int i = 0; i < 8; i++) sum += reds[i];
    float inv = 1.f / sum;
    #pragma unroll
    for (int t = 0; t < 8; t++) row[tid + 256 * t] = v[t] * inv;
}

// ---------------- context partials: stream encoder_outputs ---------------
__global__ void ctx_part_kernel(const float* __restrict__ enc,
                                const float* __restrict__ attn) {
    int b = blockIdx.x, sc = blockIdx.y, h = threadIdx.x;
    int s0 = sc * 256;
    const float* wrow = attn + b * Sd + s0;
    const float* e = enc + ((size_t)s0 * Bd + b) * Hd + h;
    float a0 = 0.f, a1 = 0.f, a2 = 0.f, a3 = 0.f;
    #pragma unroll 2
    for (int s = 0; s < 256; s += 4) {
        a0 += wrow[s + 0] * e[(size_t)(s + 0) * (Bd * Hd)];
        a1 += wrow[s + 1] * e[(size_t)(s + 1) * (Bd * Hd)];
        a2 += wrow[s + 2] * e[(size_t)(s + 2) * (Bd * Hd)];
        a3 += wrow[s + 3] * e[(size_t)(s + 3) * (Bd * Hd)];
    }
    g_ctx_part[(sc * Bd + b) * Hd + h] = (a0 + a1) + (a2 + a3);
}

__global__ void ctx_reduce_kernel(float* __restrict__ out_ctx) {
    int b = blockIdx.x, h = threadIdx.x;
    float acc = 0.f;
    #pragma unroll
    for (int sc = 0; sc < 8; sc++) acc += g_ctx_part[(sc * Bd + b) * Hd + h];
    out_ctx[b * Hd + h] = acc;
}

// ---------------- GRU cell ------------------------------------------------
__global__ void gru_kernel(const float* __restrict__ last_palette,
                           const float* __restrict__ ldh,
                           const float* __restrict__ ctx,
                           const float* __restrict__ W_ih,
                           const float* __restrict__ b_ih,
                           const float* __restrict__ W_hh,
                           const float* __restrict__ b_hh,
                           float* __restrict__ out_gru) {
    int b = blockIdx.x, tid = threadIdx.x, lane = tid & 31, warp = tid >> 5;
    __shared__ float xs[262];     // [palette(3) | context(256)]
    __shared__ float hs[Hd];
    __shared__ float gi[3 * Hd];
    __shared__ float gh[3 * Hd];
    if (tid < Pd) xs[tid] = last_palette[b * Pd + tid];
    xs[Pd + tid] = ctx[b * Hd + tid];
    hs[tid] = ldh[b * Hd + tid];
    __syncthreads();
    const int KX = Hd + Pd; // 259
    for (int k = warp; k < 3 * Hd; k += 8) {
        float a = 0.f;
        #pragma unroll
        for (int t = 0; t < 8; t++)
            a += xs[lane + 32 * t] * W_ih[k * KX + lane + 32 * t];
        if (lane < 3) a += xs[256 + lane] * W_ih[k * KX + 256 + lane];
        #pragma unroll
        for (int o = 16; o; o >>= 1) a += __shfl_xor_sync(0xffffffffu, a, o);
        if (lane == 0) gi[k] = a + b_ih[k];
        float c = 0.f;
        #pragma unroll
        for (int t = 0; t < 8; t++)
            c += hs[lane + 32 * t] * W_hh[k * Hd + lane + 32 * t];
        #pragma unroll
        for (int o = 16; o; o >>= 1) c += __shfl_xor_sync(0xffffffffu, c, o);
        if (lane == 0) gh[k] = c + b_hh[k];
    }
    __syncthreads();
    int k = tid;
    float r = sigmoidf_(gi[k] + gh[k]);
    float z = sigmoidf_(gi[Hd + k] + gh[Hd + k]);
    float n = tanhf(gi[2 * Hd + k] + r * gh[2 * Hd + k]);
    out_gru[b * Hd + k] = (1.f - z) * n + z * hs[k];
}

// ---------------- h1 = relu(gru @ W1^T + b1) ------------------------------
__global__ void h1_kernel(const float* __restrict__ gru,
                          const float* __restrict__ W1,
                          const float* __restrict__ b1) {
    int b = blockIdx.x, tid = threadIdx.x, lane = tid & 31, warp = tid >> 5;
    __shared__ float gs[Hd];
    gs[tid] = gru[b * Hd + tid];
    __syncthreads();
    for (int k = warp; k < Hd; k += 8) {
        float a = 0.f;
        #pragma unroll
        for (int t = 0; t < 8; t++)
            a += gs[lane + 32 * t] * W1[k * Hd + lane + 32 * t];
        #pragma unroll
        for (int o = 16; o; o >>= 1) a += __shfl_xor_sync(0xffffffffu, a, o);
        if (lane == 0) g_h1[b * Hd + k] = fmaxf(a + b1[k], 0.f);
    }
}

// ---------------- BatchNorm stats (training, biased var) -----------------
__global__ void bn_kernel(const float* __restrict__ gamma,
                          const float* __restrict__ beta) {
    int k = threadIdx.x; // 256 threads, one block
    float s = 0.f, sq = 0.f;
    for (int b = 0; b < Bd; b++) {
        float v = g_h1[b * Hd + k];
        s += v; sq += v * v;
    }
    float mu = s * (1.f / Bd);
    float var = sq * (1.f / Bd) - mu * mu;
    float rstd = rsqrtf(var + 1e-5f);
    float sc = rstd * gamma[k];
    g_scale[k] = sc;
    g_shift[k] = beta[k] - mu * sc;
}

// ---------------- palette = h1n @ W2^T + b2 -------------------------------
__global__ void palette_kernel(const float* __restrict__ W2,
                               const float* __restrict__ b2,
                               float* __restrict__ out_pal) {
    int b = blockIdx.x, lane = threadIdx.x & 31, p = threadIdx.x >> 5;
    if (p >= Pd) return;
    float a = 0.f;
    #pragma unroll
    for (int t = 0; t < 8; t++) {
        int h = lane + 32 * t;
        a += (g_h1[b * Hd + h] * g_scale[h] + g_shift[h]) * W2[p * Hd + h];
    }
    #pragma unroll
    for (int o = 16; o; o >>= 1) a += __shfl_xor_sync(0xffffffffu, a, o);
    if (lane == 0) out_pal[b * Pd + p] = a + b2[p];
}

// ---------------- launch ---------------------------------------------------
extern "C" void kernel_launch(void* const* d_in, const int* in_sizes, int n_in,
                              void* d_out, int out_size) {
    const float* last_palette = (const float*)d_in[0];
    const float* ldh          = (const float*)d_in[1];
    const float* enc          = (const float*)d_in[2];
    const float* We           = (const float*)d_in[3];
    const float* be           = (const float*)d_in[4];
    const float* Wh           = (const float*)d_in[5];
    const float* bh           = (const float*)d_in[6];
    const float* Wv           = (const float*)d_in[7];
    // d_in[8] = bv : softmax-invariant scalar, unused
    const float* W_ih         = (const float*)d_in[9];
    const float* b_ih         = (const float*)d_in[10];
    const float* W_hh         = (const float*)d_in[11];
    const float* b_hh         = (const float*)d_in[12];
    const float* W1           = (const float*)d_in[13];
    const float* b1           = (const float*)d_in[14];
    const float* gamma        = (const float*)d_in[15];
    const float* beta         = (const float*)d_in[16];
    const float* W2           = (const float*)d_in[17];
    const float* b2           = (const float*)d_in[18];

    float* out      = (float*)d_out;
    float* out_pal  = out;                              // [B,3]
    float* out_ctx  = out + Bd * Pd;                    // [1,B,1,H]
    float* out_gru  = out + Bd * Pd + Bd * Hd;          // [B,H]
    float* out_attn = out + Bd * Pd + 2 * Bd * Hd;      // [B,1,S]

    static bool attr_done = false;
    if (!attr_done) {
        cudaFuncSetAttribute(energy_mma_kernel,
                             cudaFuncAttributeMaxDynamicSharedMemorySize, SMEM_TOTAL);
        attr_done = true;
    }

    hid2_kernel<<<Bd, 256>>>(ldh, Wh, bh, be);
    energy_mma_kernel<<<dim3(Sd / 128, Bd), 256, SMEM_TOTAL>>>(enc, We, Wv, out_attn);
    softmax_kernel<<<Bd, 256>>>(out_attn);
    ctx_part_kernel<<<dim3(Bd, 8), 256>>>(enc, out_attn);
    ctx_reduce_kernel<<<Bd, 256>>>(out_ctx);
    gru_kernel<<<Bd, 256>>>(last_palette, ldh, out_ctx, W_ih, b_ih, W_hh, b_hh, out_gru);
    h1_kernel<<<Bd, 256>>>(out_gru, W1, b1);
    bn_kernel<<<1, 256>>>(gamma, beta);
    palette_kernel<<<Bd, 128>>>(W2, b2, out_pal);
}